// round 1
// baseline (speedup 1.0000x reference)
#include <cuda_runtime.h>
#include <math.h>

// Problem constants (fixed by the reference setup)
#define BB 4
#define NN 2048
#define CC 32
#define CONV 332.07156f

#define THREADS 256          // threads per block (pair kernel): one i per thread
#define TJ 256               // j-tile size per block
#define JC (NN / TJ)         // 8 j-chunks
#define ITILES (NN / THREADS)// 8 i-tiles

// Scratch (no cudaMalloc allowed)
__device__ double g_pair[BB];
__device__ double g_self[BB];
__device__ float  g_si[BB * NN];
__device__ float  g_sj[BB * NN];

__global__ void init_kernel() {
    int t = threadIdx.x;
    if (t < BB) { g_pair[t] = 0.0; g_self[t] = 0.0; }
}

// Per-atom precompute: s_i, s_j, and E_self reduction per batch.
// One thread per atom (B*N = 8192 threads).
__global__ void precompute_kernel(const float* __restrict__ embs,
                                  const float* __restrict__ qs,
                                  const float* __restrict__ born,
                                  const float* __restrict__ die,
                                  const float* __restrict__ filt) {
    int idx = blockIdx.x * blockDim.x + threadIdx.x;
    if (idx >= BB * NN) return;
    const float* e = embs + (long)idx * CC;

    float ad = 0.f, R = 0.f, si = 0.f, sj = 0.f;
#pragma unroll
    for (int c = 0; c < CC; c++) {
        float ec = e[c];
        ad += ec * die[c];
        R  += ec * born[c];
        si += ec * filt[c];
        sj += ec * filt[CC + c];
    }
    ad += 1e-6f;
    R  += 1.0f;
    float es = -(1.0f - 1.0f / ad) * qs[idx] / (R + 1e-6f);

    g_si[idx] = si;
    g_sj[idx] = sj;

    // warp reduce E_self (a warp never straddles batches: N = 2048 is a
    // multiple of 32 and idx is contiguous within the warp)
#pragma unroll
    for (int off = 16; off > 0; off >>= 1)
        es += __shfl_down_sync(0xffffffffu, es, off);
    if ((threadIdx.x & 31) == 0) {
        int b = idx / NN;
        atomicAdd(&g_self[b], (double)es);
    }
}

// Pairwise kernel: block = (i-tile of 256 rows) x (j-chunk of 256 cols) x batch.
// grid = (ITILES * JC, BB) = (64, 4) = 256 blocks.
__global__ void __launch_bounds__(THREADS)
pair_kernel(const float* __restrict__ X,
            const float* __restrict__ filt) {
    __shared__ float xs[TJ], ys[TJ], zs[TJ], sjj[TJ];

    const int b     = blockIdx.y;
    const int itile = blockIdx.x / JC;
    const int jc    = blockIdx.x % JC;
    const int tid   = threadIdx.x;

    const float wd = filt[2 * CC];   // == 1.0 per setup, but read it anyway

    // load j tile into shared (SoA for conflict-free broadcast reads)
    {
        int j  = jc * TJ + tid;
        long g = (long)b * NN + j;
        xs[tid]  = X[g * 3 + 0];
        ys[tid]  = X[g * 3 + 1];
        zs[tid]  = X[g * 3 + 2];
        sjj[tid] = g_sj[g];
    }
    __syncthreads();

    // this thread's i row
    const int i  = itile * THREADS + tid;
    const long gi = (long)b * NN + i;
    const float xi = X[gi * 3 + 0];
    const float yi = X[gi * 3 + 1];
    const float zi = X[gi * 3 + 2];
    const float si = g_si[gi];

    float acc = 0.0f;
#pragma unroll 8
    for (int j = 0; j < TJ; j++) {
        float dx = xi - xs[j];
        float dy = yi - ys[j];
        float dz = zi - zs[j];
        // reference adds 1e-6 per component before the sum -> +3e-6
        float d2 = fmaf(dx, dx, fmaf(dy, dy, fmaf(dz, dz, 3e-6f)));
        float D  = sqrtf(d2);
        float invD = 1.0f / (D + 1e-6f);
        acc += (si + sjj[j] + wd * D) * invD;
    }

    // warp reduce, then one double atomic per warp
#pragma unroll
    for (int off = 16; off > 0; off >>= 1)
        acc += __shfl_down_sync(0xffffffffu, acc, off);
    if ((tid & 31) == 0)
        atomicAdd(&g_pair[b], (double)acc);
}

__global__ void finalize_kernel(float* __restrict__ out) {
    int b = threadIdx.x;
    if (b < BB) {
        float v = CONV * ((float)g_self[b] + 0.5f * (float)g_pair[b]) * 0.01f;
        if (isnan(v)) v = 1e-6f;
        out[b] = v;
    }
}

extern "C" void kernel_launch(void* const* d_in, const int* in_sizes, int n_in,
                              void* d_out, int out_size) {
    const float* X    = (const float*)d_in[0];  // (B,N,3)
    const float* embs = (const float*)d_in[1];  // (B,N,C)
    const float* qs   = (const float*)d_in[2];  // (B,N)
    // d_in[3] = paired_mask (unused by reference)
    const float* born = (const float*)d_in[4];  // (C,)
    const float* die  = (const float*)d_in[5];  // (C,)
    const float* filt = (const float*)d_in[6];  // (2C+1, 1)
    float* out = (float*)d_out;

    init_kernel<<<1, 32>>>();
    precompute_kernel<<<(BB * NN + 255) / 256, 256>>>(embs, qs, born, die, filt);
    dim3 grid(ITILES * JC, BB);
    pair_kernel<<<grid, THREADS>>>(X, filt);
    finalize_kernel<<<1, 32>>>(out);
}

// round 2
// speedup vs baseline: 1.1951x; 1.1951x over previous
#include <cuda_runtime.h>
#include <math.h>

// Problem constants (fixed by the reference setup)
#define BB 4
#define NN 2048
#define CC 32
#define CONV 332.07156f

#define THREADS 256
#define TJ 256
#define JC 8            // j-chunks per batch
#define ITILES 8        // i-tiles per batch
#define NBLOCKS (BB * ITILES * JC)   // 256

// Scratch (no cudaMalloc allowed)
__device__ double g_part_pair[NBLOCKS];
__device__ double g_part_self[NBLOCKS];
__device__ unsigned int g_counter = 0;   // reset by last block each run

__global__ void __launch_bounds__(THREADS, 2)
fused_kernel(const float* __restrict__ X,
             const float* __restrict__ embs,
             const float* __restrict__ qs,
             const float* __restrict__ born,
             const float* __restrict__ die,
             const float* __restrict__ filt,
             float* __restrict__ out)
{
    __shared__ float4 tile[TJ];          // {x, y, z, s_j}
    __shared__ double red_pair[8], red_self[8];
    __shared__ double fin_p[8], fin_s[8];
    __shared__ bool isLast;

    const int tid   = threadIdx.x;
    const int blk   = blockIdx.x;
    const int b     = blk / (ITILES * JC);
    const int rem   = blk % (ITILES * JC);
    const int itile = rem / JC;
    const int jc    = rem % JC;

    const float wd = filt[2 * CC];

    // ---- j tile: position + s_j (this block's 256 j's) ----
    {
        int  j  = jc * TJ + tid;
        long gj = (long)b * NN + j;
        const float* e = embs + gj * CC;
        float sj = 0.f;
#pragma unroll
        for (int c = 0; c < CC; c++) sj = fmaf(e[c], filt[CC + c], sj);
        tile[tid] = make_float4(X[gj * 3 + 0], X[gj * 3 + 1], X[gj * 3 + 2], sj);
    }

    // ---- i row: s_i  (+ E_self only on jc==0 blocks, each i covered once) ----
    const int  i  = itile * THREADS + tid;
    const long gi = (long)b * NN + i;
    float si = 0.f, es = 0.f;
    {
        const float* e = embs + gi * CC;
#pragma unroll
        for (int c = 0; c < CC; c++) si = fmaf(e[c], filt[c], si);
        if (jc == 0) {
            float ad = 1e-6f, R = 1.0f;
#pragma unroll
            for (int c = 0; c < CC; c++) {
                float ec = e[c];
                ad = fmaf(ec, die[c], ad);
                R  = fmaf(ec, born[c], R);
            }
            es = -(1.0f - 1.0f / ad) * qs[gi] / (R + 1e-6f);
        }
    }
    const float xi = X[gi * 3 + 0];
    const float yi = X[gi * 3 + 1];
    const float zi = X[gi * 3 + 2];
    // E_pair = (s_i + s_j + wd*D)/(D+eps) = (s_i - wd*eps + s_j)*invD + wd   (EXACT)
    const float sip = si - wd * 1e-6f;

    __syncthreads();

    float acc = 0.0f;
#pragma unroll 8
    for (int j = 0; j < TJ; j++) {
        float4 p = tile[j];
        float dx = xi - p.x;
        float dy = yi - p.y;
        float dz = zi - p.z;
        float d2 = fmaf(dx, dx, fmaf(dy, dy, fmaf(dz, dz, 3e-6f)));
        float r  = rsqrtf(d2);                      // 1 MUFU per pair
        // 1/(D+eps) = r/(1+eps*r) ~= r*(1 - eps*r), rel err <= (eps*r)^2 ~ 3e-7
        float invD = r * fmaf(-1e-6f, r, 1.0f);
        acc = fmaf(sip + p.w, invD, acc);
    }

    // ---- block reduce (pair partial + self partial) ----
#pragma unroll
    for (int off = 16; off > 0; off >>= 1) {
        acc += __shfl_down_sync(0xffffffffu, acc, off);
        es  += __shfl_down_sync(0xffffffffu, es,  off);
    }
    if ((tid & 31) == 0) { red_pair[tid >> 5] = acc; red_self[tid >> 5] = es; }
    __syncthreads();
    if (tid == 0) {
        double p = 0.0, s = 0.0;
#pragma unroll
        for (int w = 0; w < 8; w++) { p += red_pair[w]; s += red_self[w]; }
        g_part_pair[blk] = p;
        g_part_self[blk] = s;
        __threadfence();
        unsigned int t = atomicAdd(&g_counter, 1u);
        isLast = (t == (unsigned)(gridDim.x - 1));
    }
    __syncthreads();
    if (!isLast) return;

    // ---- finalize (last block): sum 64 partials per batch ----
    double pp = __ldcg(&g_part_pair[tid]);   // blk index == tid (256 == 256)
    double ss = __ldcg(&g_part_self[tid]);
#pragma unroll
    for (int off = 16; off > 0; off >>= 1) {
        pp += __shfl_down_sync(0xffffffffu, pp, off);
        ss += __shfl_down_sync(0xffffffffu, ss, off);
    }
    if ((tid & 31) == 0) { fin_p[tid >> 5] = pp; fin_s[tid >> 5] = ss; }
    __syncthreads();
    if (tid < BB) {
        // 64 consecutive blocks per batch -> warps 2b and 2b+1
        double pair = fin_p[2 * tid] + fin_p[2 * tid + 1]
                    + (double)wd * (double)NN * (double)NN;   // + Sum(wd) closed form
        double self = fin_s[2 * tid] + fin_s[2 * tid + 1];
        float v = (float)((double)CONV * (self + 0.5 * pair) * 0.01);
        if (isnan(v)) v = 1e-6f;
        out[tid] = v;
    }
    if (tid == 0) g_counter = 0;   // reset for next graph replay
}

extern "C" void kernel_launch(void* const* d_in, const int* in_sizes, int n_in,
                              void* d_out, int out_size) {
    const float* X    = (const float*)d_in[0];  // (B,N,3)
    const float* embs = (const float*)d_in[1];  // (B,N,C)
    const float* qs   = (const float*)d_in[2];  // (B,N)
    // d_in[3] = paired_mask (unused by reference)
    const float* born = (const float*)d_in[4];  // (C,)
    const float* die  = (const float*)d_in[5];  // (C,)
    const float* filt = (const float*)d_in[6];  // (2C+1, 1)
    float* out = (float*)d_out;

    fused_kernel<<<NBLOCKS, THREADS>>>(X, embs, qs, born, die, filt, out);
}

// round 3
// speedup vs baseline: 1.4200x; 1.1882x over previous
#include <cuda_runtime.h>
#include <math.h>

// Problem constants (fixed by the reference setup)
#define BB 4
#define NN 2048
#define CC 32
#define CONV 332.07156f

#define THREADS 256
#define IB 4                      // i-atoms per thread
#define IBLK (THREADS * IB)       // 1024 i per block
#define ITILES (NN / IBLK)        // 2
#define TJ 64                     // j-tile per block
#define JC (NN / TJ)              // 32
#define NBLOCKS (BB * ITILES * JC) // 256

// Scratch (no cudaMalloc allowed)
__device__ double g_part_pair[NBLOCKS];
__device__ double g_part_self[NBLOCKS];
__device__ unsigned int g_counter = 0;

__global__ void __launch_bounds__(THREADS, 2)
fused_kernel(const float* __restrict__ X,
             const float* __restrict__ embs,
             const float* __restrict__ qs,
             const float* __restrict__ born,
             const float* __restrict__ die,
             const float* __restrict__ filt,
             float* __restrict__ out)
{
    __shared__ float4 tile[TJ];          // {x, y, z, s_j}
    __shared__ double red_pair[8], red_self[8];
    __shared__ double fin_p[8], fin_s[8];
    __shared__ bool isLast;

    const int tid   = threadIdx.x;
    const int blk   = blockIdx.x;
    const int b     = blk / (ITILES * JC);
    const int rem   = blk % (ITILES * JC);
    const int itile = rem / JC;
    const int jc    = rem % JC;

    const float wd = filt[2 * CC];

    // ---- j tile: position + s_j (threads 0..TJ-1) ----
    if (tid < TJ) {
        int  j  = jc * TJ + tid;
        long gj = (long)b * NN + j;
        const float4* e4 = (const float4*)(embs + gj * CC);
        const float4* f4 = (const float4*)(filt + CC);
        float sj = 0.f;
#pragma unroll
        for (int c = 0; c < CC / 4; c++) {
            float4 e = e4[c], f = f4[c];
            sj = fmaf(e.x, f.x, fmaf(e.y, f.y, fmaf(e.z, f.z, fmaf(e.w, f.w, sj))));
        }
        tile[tid] = make_float4(X[gj * 3 + 0], X[gj * 3 + 1], X[gj * 3 + 2], sj);
    }

    // ---- this thread's IB i-rows: positions, s_i (+E_self on jc==0) ----
    float xi[IB], yi[IB], zi[IB], sip[IB], acc[IB];
    float es = 0.f;
#pragma unroll
    for (int k = 0; k < IB; k++) {
        const int  i  = itile * IBLK + k * THREADS + tid;
        const long gi = (long)b * NN + i;
        const float4* e4 = (const float4*)(embs + gi * CC);
        const float4* fi4 = (const float4*)(filt);
        float si = 0.f;
#pragma unroll
        for (int c = 0; c < CC / 4; c++) {
            float4 e = e4[c], f = fi4[c];
            si = fmaf(e.x, f.x, fmaf(e.y, f.y, fmaf(e.z, f.z, fmaf(e.w, f.w, si))));
        }
        if (jc == 0) {
            const float4* d4 = (const float4*)(die);
            const float4* b4 = (const float4*)(born);
            float ad = 1e-6f, R = 1.0f;
#pragma unroll
            for (int c = 0; c < CC / 4; c++) {
                float4 e = e4[c], d = d4[c], bo = b4[c];
                ad = fmaf(e.x, d.x, fmaf(e.y, d.y, fmaf(e.z, d.z, fmaf(e.w, d.w, ad))));
                R  = fmaf(e.x, bo.x, fmaf(e.y, bo.y, fmaf(e.z, bo.z, fmaf(e.w, bo.w, R))));
            }
            es += -(1.0f - 1.0f / ad) * qs[gi] / (R + 1e-6f);
        }
        xi[k] = X[gi * 3 + 0];
        yi[k] = X[gi * 3 + 1];
        zi[k] = X[gi * 3 + 2];
        // E_pair = (s_i + s_j + wd*D)/(D+eps) = (s_i - wd*eps + s_j)*invD + wd  (EXACT)
        sip[k] = si - wd * 1e-6f;
        acc[k] = 0.f;
    }

    __syncthreads();

    // ---- main loop: 1 LDS.128 feeds IB=4 pairs; 4 independent MUFU chains ----
#pragma unroll 2
    for (int j = 0; j < TJ; j++) {
        float4 p = tile[j];
#pragma unroll
        for (int k = 0; k < IB; k++) {
            float dx = xi[k] - p.x;
            float dy = yi[k] - p.y;
            float dz = zi[k] - p.z;
            float d2 = fmaf(dx, dx, fmaf(dy, dy, fmaf(dz, dz, 3e-6f)));
            float r  = rsqrtf(d2);
            // 1/(D+eps) = r/(1+eps*r) ~= r*(1 - eps*r), rel err <= (eps*r)^2 ~ 3e-7
            float invD = r * fmaf(-1e-6f, r, 1.0f);
            acc[k] = fmaf(sip[k] + p.w, invD, acc[k]);
        }
    }

    float accs = (acc[0] + acc[1]) + (acc[2] + acc[3]);

    // ---- block reduce ----
#pragma unroll
    for (int off = 16; off > 0; off >>= 1) {
        accs += __shfl_down_sync(0xffffffffu, accs, off);
        es   += __shfl_down_sync(0xffffffffu, es,   off);
    }
    if ((tid & 31) == 0) { red_pair[tid >> 5] = accs; red_self[tid >> 5] = es; }
    __syncthreads();
    if (tid == 0) {
        double p = 0.0, s = 0.0;
#pragma unroll
        for (int w = 0; w < 8; w++) { p += red_pair[w]; s += red_self[w]; }
        g_part_pair[blk] = p;
        g_part_self[blk] = s;
        __threadfence();
        unsigned int t = atomicAdd(&g_counter, 1u);
        isLast = (t == (unsigned)(gridDim.x - 1));
    }
    __syncthreads();
    if (!isLast) return;

    // ---- finalize (last block): 256 partials, 64 consecutive per batch ----
    double pp = __ldcg(&g_part_pair[tid]);
    double ss = __ldcg(&g_part_self[tid]);
#pragma unroll
    for (int off = 16; off > 0; off >>= 1) {
        pp += __shfl_down_sync(0xffffffffu, pp, off);
        ss += __shfl_down_sync(0xffffffffu, ss, off);
    }
    if ((tid & 31) == 0) { fin_p[tid >> 5] = pp; fin_s[tid >> 5] = ss; }
    __syncthreads();
    if (tid < BB) {
        double pair = fin_p[2 * tid] + fin_p[2 * tid + 1]
                    + (double)wd * (double)NN * (double)NN;   // + Sum(wd) closed form
        double self = fin_s[2 * tid] + fin_s[2 * tid + 1];
        float v = (float)((double)CONV * (self + 0.5 * pair) * 0.01);
        if (isnan(v)) v = 1e-6f;
        out[tid] = v;
    }
    if (tid == 0) g_counter = 0;   // reset for next graph replay
}

extern "C" void kernel_launch(void* const* d_in, const int* in_sizes, int n_in,
                              void* d_out, int out_size) {
    const float* X    = (const float*)d_in[0];  // (B,N,3)
    const float* embs = (const float*)d_in[1];  // (B,N,C)
    const float* qs   = (const float*)d_in[2];  // (B,N)
    // d_in[3] = paired_mask (unused by reference)
    const float* born = (const float*)d_in[4];  // (C,)
    const float* die  = (const float*)d_in[5];  // (C,)
    const float* filt = (const float*)d_in[6];  // (2C+1, 1)
    float* out = (float*)d_out;

    fused_kernel<<<NBLOCKS, THREADS>>>(X, embs, qs, born, die, filt, out);
}

// round 4
// speedup vs baseline: 1.8150x; 1.2782x over previous
#include <cuda_runtime.h>
#include <math.h>

// Problem constants (fixed by the reference setup)
#define BB 4
#define NN 2048
#define CC 32
#define CONV 332.07156f
#define EPS 1e-6f

// ---- precompute kernel geometry ----
#define PRE_THREADS 256
#define PRE_BLOCKS (BB * NN / PRE_THREADS)   // 32  (8 blocks per batch)

// ---- pair kernel geometry ----
#define PTHREADS 128
#define PIB 8                     // i-atoms per thread -> 1024 i per panel
#define PANELS (BB * 2)           // 8 panels of 1024 i-rows
#define SPLITS 37                 // j-splits per panel (runtime-sized ranges)
#define PBLOCKS (PANELS * SPLITS) // 296 = 2 per SM on 148 SMs

// Scratch (no cudaMalloc allowed)
__device__ float4 g_P[BB * NN];          // {x, y, z, w'=s_i+s_j-wd*eps}
__device__ double g_part_pair[PBLOCKS];
__device__ double g_part_self[PRE_BLOCKS];
__device__ unsigned int g_counter = 0;

// ============ kernel 1: per-atom precompute + E_self partials ============
__global__ void __launch_bounds__(PRE_THREADS)
precompute_kernel(const float* __restrict__ X,
                  const float* __restrict__ embs,
                  const float* __restrict__ qs,
                  const float* __restrict__ born,
                  const float* __restrict__ die,
                  const float* __restrict__ filt)
{
    __shared__ double red[PRE_THREADS / 32];
    const int tid = threadIdx.x;
    const int idx = blockIdx.x * PRE_THREADS + tid;
    const float wd = filt[2 * CC];

    const float4* e4 = (const float4*)(embs + (long)idx * CC);
    const float4* fi = (const float4*)(filt);
    const float4* fj = (const float4*)(filt + CC);
    const float4* d4 = (const float4*)(die);
    const float4* b4 = (const float4*)(born);

    float si = 0.f, sj = 0.f, ad = EPS, R = 1.0f;
#pragma unroll
    for (int c = 0; c < CC / 4; c++) {
        float4 e = e4[c];
        float4 a = fi[c], bq = fj[c], d = d4[c], bo = b4[c];
        si = fmaf(e.x, a.x,  fmaf(e.y, a.y,  fmaf(e.z, a.z,  fmaf(e.w, a.w,  si))));
        sj = fmaf(e.x, bq.x, fmaf(e.y, bq.y, fmaf(e.z, bq.z, fmaf(e.w, bq.w, sj))));
        ad = fmaf(e.x, d.x,  fmaf(e.y, d.y,  fmaf(e.z, d.z,  fmaf(e.w, d.w,  ad))));
        R  = fmaf(e.x, bo.x, fmaf(e.y, bo.y, fmaf(e.z, bo.z, fmaf(e.w, bo.w, R))));
    }
    float es = -(1.0f - 1.0f / ad) * qs[idx] / (R + EPS);

    g_P[idx] = make_float4(X[idx * 3 + 0], X[idx * 3 + 1], X[idx * 3 + 2],
                           si + sj - wd * EPS);

    // block never straddles batches (256 | 2048)
#pragma unroll
    for (int off = 16; off > 0; off >>= 1)
        es += __shfl_down_sync(0xffffffffu, es, off);
    if ((tid & 31) == 0) red[tid >> 5] = (double)es;
    __syncthreads();
    if (tid == 0) {
        double s = 0.0;
#pragma unroll
        for (int w = 0; w < PRE_THREADS / 32; w++) s += red[w];
        g_part_self[blockIdx.x] = s;
    }
}

// ============ kernel 2: pairwise rowsums (+finalize in last block) ============
// E_pair(batch) = sum_i w'_i * (acc1_i - eps*acc2_i) + wd * N^2
// where acc1_i = sum_j r_ij, acc2_i = sum_j r_ij^2, r = rsqrt(|xi-xj|^2+3e-6)
__global__ void __launch_bounds__(PTHREADS, 2)
pair_kernel(const float* __restrict__ filt, float* __restrict__ out)
{
    __shared__ double red[PTHREADS / 32];
    __shared__ bool isLast;

    const int tid = threadIdx.x;
    const int blk = blockIdx.x;
    const int p   = blk / SPLITS;          // panel 0..7
    const int jj  = blk % SPLITS;
    const int b   = p >> 1;
    const int itile = p & 1;
    const int j0 = (jj * NN) / SPLITS;
    const int j1 = ((jj + 1) * NN) / SPLITS;

    const float4* __restrict__ P = g_P + b * NN;
    const int ibase = itile * (PTHREADS * PIB) + tid;

    float xi[PIB], yi[PIB], zi[PIB], acc1[PIB], acc2[PIB];
#pragma unroll
    for (int k = 0; k < PIB; k++) {
        float4 q = __ldg(&P[ibase + k * PTHREADS]);
        xi[k] = q.x; yi[k] = q.y; zi[k] = q.z;
        acc1[k] = 0.f; acc2[k] = 0.f;
    }

#pragma unroll 4
    for (int j = j0; j < j1; j++) {
        float4 pj = __ldg(&P[j]);           // warp-uniform -> L1 broadcast
#pragma unroll
        for (int k = 0; k < PIB; k++) {
            float dx = xi[k] - pj.x;
            float dy = yi[k] - pj.y;
            float dz = zi[k] - pj.z;
            float d2 = fmaf(dx, dx, fmaf(dy, dy, fmaf(dz, dz, 3e-6f)));
            float r  = rsqrtf(d2);
            acc1[k] += r;
            acc2[k]  = fmaf(r, r, acc2[k]);
        }
    }

    // weight by w'_i, combine in double
    double part = 0.0;
#pragma unroll
    for (int k = 0; k < PIB; k++) {
        float w = __ldg(&P[ibase + k * PTHREADS]).w;
        part += (double)w * ((double)acc1[k] - (double)EPS * (double)acc2[k]);
    }
#pragma unroll
    for (int off = 16; off > 0; off >>= 1)
        part += __shfl_down_sync(0xffffffffu, part, off);
    if ((tid & 31) == 0) red[tid >> 5] = part;
    __syncthreads();
    if (tid == 0) {
        double s = 0.0;
#pragma unroll
        for (int w = 0; w < PTHREADS / 32; w++) s += red[w];
        g_part_pair[blk] = s;
        __threadfence();
        unsigned int t = atomicAdd(&g_counter, 1u);
        isLast = (t == (unsigned)(gridDim.x - 1));
    }
    __syncthreads();
    if (!isLast) return;

    // ---- finalize: warp w handles batch w ----
    const int w = tid >> 5, lane = tid & 31;
    const float wd = filt[2 * CC];

    // pair partials for batch w: indices [w*74, w*74+74)
    double pp = 0.0;
#pragma unroll
    for (int t = 0; t < 3; t++) {
        int idx = lane + t * 32;
        if (idx < 2 * SPLITS) pp += __ldcg(&g_part_pair[w * 2 * SPLITS + idx]);
    }
    // self partials for batch w: indices [w*8, w*8+8)
    double ss = (lane < PRE_BLOCKS / BB)
              ? __ldcg(&g_part_self[w * (PRE_BLOCKS / BB) + lane]) : 0.0;
#pragma unroll
    for (int off = 16; off > 0; off >>= 1) {
        pp += __shfl_down_sync(0xffffffffu, pp, off);
        ss += __shfl_down_sync(0xffffffffu, ss, off);
    }
    if (lane == 0) {
        double pair = pp + (double)wd * (double)NN * (double)NN;
        float v = (float)((double)CONV * (ss + 0.5 * pair) * 0.01);
        if (isnan(v)) v = 1e-6f;
        out[w] = v;
    }
    if (tid == 0) g_counter = 0;   // reset for next graph replay
}

extern "C" void kernel_launch(void* const* d_in, const int* in_sizes, int n_in,
                              void* d_out, int out_size) {
    const float* X    = (const float*)d_in[0];  // (B,N,3)
    const float* embs = (const float*)d_in[1];  // (B,N,C)
    const float* qs   = (const float*)d_in[2];  // (B,N)
    // d_in[3] = paired_mask (unused by reference)
    const float* born = (const float*)d_in[4];  // (C,)
    const float* die  = (const float*)d_in[5];  // (C,)
    const float* filt = (const float*)d_in[6];  // (2C+1, 1)
    float* out = (float*)d_out;

    precompute_kernel<<<PRE_BLOCKS, PRE_THREADS>>>(X, embs, qs, born, die, filt);
    pair_kernel<<<PBLOCKS, PTHREADS>>>(filt, out);
}